// round 6
// baseline (speedup 1.0000x reference)
#include <cuda_runtime.h>
#include <stdint.h>

// BinarizedLinear: act[d,o] = sum_i W[d,o,i] * x[d,i];  out[d,o] = (act > bias[d,o]) ? 1.0 : 0.0
// D=64, OUT=2048, IN=2048. All buffers float32.
//
// R6: single-wave persistent variant of the roofline R2 kernel.
//   - 1024 CTAs x 256 threads -> one wave on 148 SMs (no wave transitions).
//   - Each block owns 128 consecutive rows of ONE direction: x staged to smem once,
//     then 16 tiles x 8 rows streamed back-to-back with no further syncs.
//   - Eliminates ~13 wave boundaries' worth of launch/drain/x-restage DRAM bubbles.

#define D_DIRS 64
#define OUT_F  2048
#define IN_F   2048
#define WARPS  8
#define THREADS (WARPS * 32)
#define BLOCKS_PER_D 16                       // 2048 rows / 128 rows-per-block
#define ROWS_PER_BLOCK 128
#define TILES  (ROWS_PER_BLOCK / WARPS)       // 16 iterations of 8 rows

__global__ __launch_bounds__(THREADS)
void binlin_kernel(const float* __restrict__ W,
                   const float* __restrict__ x,
                   const float* __restrict__ bias,
                   float* __restrict__ out)
{
    __shared__ float xf[IN_F];

    const int d    = blockIdx.x / BLOCKS_PER_D;
    const int rbase = (blockIdx.x % BLOCKS_PER_D) * ROWS_PER_BLOCK;

    // Stage x[d,:] once per block (read-only afterwards -> no more syncs).
    const float4* xr4 = (const float4*)(x + (size_t)d * IN_F);
    float4*       xs4 = (float4*)xf;
    #pragma unroll
    for (int i = threadIdx.x; i < IN_F / 4; i += THREADS)
        xs4[i] = xr4[i];
    __syncthreads();

    const int warp = threadIdx.x >> 5;
    const int lane = threadIdx.x & 31;

    // Preload this lane's x slice into registers: reused across all 16 rows,
    // removes LDS traffic from the inner stream entirely.
    float4 xv[16];
    #pragma unroll
    for (int it = 0; it < 16; ++it)
        xv[it] = *(const float4*)(&xf[it * 128 + lane * 4]);

    for (int t = 0; t < TILES; ++t) {
        const int o = rbase + t * WARPS + warp;
        const float4* __restrict__ wr =
            (const float4*)(W + ((size_t)d * OUT_F + o) * IN_F);

        float acc = 0.0f;
        #pragma unroll
        for (int it = 0; it < 16; ++it) {
            float4 w = __ldg(&wr[it * 32 + lane]);
            acc = fmaf(w.x, xv[it].x, acc);
            acc = fmaf(w.y, xv[it].y, acc);
            acc = fmaf(w.z, xv[it].z, acc);
            acc = fmaf(w.w, xv[it].w, acc);
        }

        #pragma unroll
        for (int s = 16; s > 0; s >>= 1)
            acc += __shfl_xor_sync(0xFFFFFFFFu, acc, s);

        if (lane == 0) {
            const int idx = d * OUT_F + o;
            out[idx] = (acc > bias[idx]) ? 1.0f : 0.0f;
        }
    }
}

extern "C" void kernel_launch(void* const* d_in, const int* in_sizes, int n_in,
                              void* d_out, int out_size)
{
    const float* W    = (const float*)d_in[0];
    const float* x    = (const float*)d_in[1];
    const float* bias = (const float*)d_in[2];
    float*       out  = (float*)d_out;

    const int grid = D_DIRS * BLOCKS_PER_D;   // 1024 CTAs -> single wave
    binlin_kernel<<<grid, THREADS>>>(W, x, bias, out);
}